// round 1
// baseline (speedup 1.0000x reference)
#include <cuda_runtime.h>
#include <math.h>

#define NQ      10
#define NST     1024        // 2^NQ
#define NL      3
#define THREADS 512

__device__ __forceinline__ float2 cmul(float2 a, float2 b) {
    return make_float2(a.x * b.x - a.y * b.y, a.x * b.y + a.y * b.x);
}

__global__ __launch_bounds__(THREADS)
void qgan_kernel(const float* __restrict__ z,       // [B, 10]
                 const float* __restrict__ weights, // [3, 10, 3]
                 const float* __restrict__ W1,      // [10, 32]
                 const float* __restrict__ b1,      // [32]
                 const float* __restrict__ W2,      // [32, 16]
                 const float* __restrict__ b2,      // [16]
                 const float* __restrict__ W3,      // [16, 1]
                 const float* __restrict__ b3,      // [1]
                 float* __restrict__ out)           // [B, 1]
{
    __shared__ float2 st[NST];          // statevector
    __shared__ float2 U[NL * NQ * 4];   // 2x2 complex unitaries
    __shared__ float  ry_c[NQ], ry_s[NQ];
    __shared__ float  red[16][NQ];      // per-warp feature partials
    __shared__ float  feats[NQ];
    __shared__ float  h1[32];
    __shared__ float  h2[16];

    const int b   = blockIdx.x;
    const int tid = threadIdx.x;

    // --- Build U[l][i] from weights: U = [[cb*cis(-(a+c)/2), -sb*cis((a-c)/2)],
    //                                      [sb*cis((c-a)/2),   cb*cis((a+c)/2)]]
    if (tid < NL * NQ) {
        float a  = weights[tid * 3 + 0];
        float bb = weights[tid * 3 + 1];
        float c  = weights[tid * 3 + 2];
        float cb, sb;  __sincosf(0.5f * bb, &sb, &cb);
        float apc = 0.5f * (a + c), amc = 0.5f * (a - c);
        float capc, sapc, camc, samc;
        __sincosf(apc, &sapc, &capc);
        __sincosf(amc, &samc, &camc);
        U[tid * 4 + 0] = make_float2( cb * capc, -cb * sapc);
        U[tid * 4 + 1] = make_float2(-sb * camc, -sb * samc);
        U[tid * 4 + 2] = make_float2( sb * camc, -sb * samc);
        U[tid * 4 + 3] = make_float2( cb * capc,  cb * sapc);
    }
    // --- RY angles (clip z to [-1,1])
    if (tid >= 64 && tid < 64 + NQ) {
        int i = tid - 64;
        float zv = z[b * NQ + i];
        zv = fminf(fmaxf(zv, -1.0f), 1.0f);
        float s, c; __sincosf(0.5f * zv, &s, &c);
        ry_c[i] = c;  ry_s[i] = s;
    }
    // --- init |0...0>
    st[tid]       = make_float2(tid == 0 ? 1.0f : 0.0f, 0.0f);
    st[tid + 512] = make_float2(0.0f, 0.0f);
    __syncthreads();

    // --- RY layer (real rotation on each wire)
    for (int w = 0; w < NQ; w++) {
        const int k  = 9 - w;
        const int s  = 1 << k;
        const int i0 = ((tid >> k) << (k + 1)) | (tid & (s - 1));
        const int i1 = i0 | s;
        const float c = ry_c[w], si = ry_s[w];
        float2 a0 = st[i0], a1 = st[i1];
        st[i0] = make_float2(c * a0.x - si * a1.x, c * a0.y - si * a1.y);
        st[i1] = make_float2(si * a0.x + c * a1.x, si * a0.y + c * a1.y);
        __syncthreads();
    }

    // --- layers: 10 single-qubit unitaries, then 9 CNOTs (sequential)
    for (int l = 0; l < NL; l++) {
        for (int w = 0; w < NQ; w++) {
            const int k  = 9 - w;
            const int s  = 1 << k;
            const int i0 = ((tid >> k) << (k + 1)) | (tid & (s - 1));
            const int i1 = i0 | s;
            const int ub = (l * NQ + w) * 4;
            float2 u00 = U[ub + 0], u01 = U[ub + 1];
            float2 u10 = U[ub + 2], u11 = U[ub + 3];
            float2 a0 = st[i0], a1 = st[i1];
            float2 n0 = cmul(u00, a0), t0 = cmul(u01, a1);
            float2 n1 = cmul(u10, a0), t1 = cmul(u11, a1);
            n0.x += t0.x; n0.y += t0.y;
            n1.x += t1.x; n1.y += t1.y;
            st[i0] = n0;  st[i1] = n1;
            __syncthreads();
        }
        for (int cw = 0; cw < NQ - 1; cw++) {
            const int k = 9 - cw;           // ctrl bit position; target = k-1
            if (tid < 256) {
                const int low = tid & ((1 << (k - 1)) - 1);
                const int hi  = tid >> (k - 1);
                const int i0  = (hi << (k + 1)) | (1 << k) | low;  // ctrl=1,tgt=0
                const int i1  = i0 | (1 << (k - 1));               // ctrl=1,tgt=1
                float2 a = st[i0], c2 = st[i1];
                st[i0] = c2;  st[i1] = a;
            }
            __syncthreads();
        }
    }

    // --- features: <Z_i> = sum_idx |amp|^2 * (bit_i(idx)==0 ? +1 : -1)
    float f[NQ];
#pragma unroll
    for (int i = 0; i < NQ; i++) f[i] = 0.0f;
#pragma unroll
    for (int r = 0; r < 2; r++) {
        const int idx = tid + r * 512;
        float2 a = st[idx];
        float p = a.x * a.x + a.y * a.y;
#pragma unroll
        for (int i = 0; i < NQ; i++)
            f[i] += ((idx >> (9 - i)) & 1) ? -p : p;
    }
#pragma unroll
    for (int i = 0; i < NQ; i++) {
#pragma unroll
        for (int o = 16; o > 0; o >>= 1)
            f[i] += __shfl_xor_sync(0xffffffff, f[i], o);
    }
    const int warp = tid >> 5, lane = tid & 31;
    if (lane == 0) {
#pragma unroll
        for (int i = 0; i < NQ; i++) red[warp][i] = f[i];
    }
    __syncthreads();
    if (tid < NQ) {
        float s = 0.0f;
#pragma unroll
        for (int wp = 0; wp < 16; wp++) s += red[wp][tid];
        feats[tid] = s;
    }
    __syncthreads();

    // --- MLP: 10 -> 32 -> 16 -> 1
    if (tid < 32) {
        float acc = b1[tid];
#pragma unroll
        for (int i = 0; i < NQ; i++) acc += feats[i] * W1[i * 32 + tid];
        h1[tid] = tanhf(acc);
    }
    __syncthreads();
    if (tid < 16) {
        float acc = b2[tid];
#pragma unroll
        for (int i = 0; i < 32; i++) acc += h1[i] * W2[i * 16 + tid];
        h2[tid] = tanhf(acc);
    }
    __syncthreads();
    if (tid == 0) {
        float acc = b3[0];
#pragma unroll
        for (int i = 0; i < 16; i++) acc += h2[i] * W3[i];
        float sg = 1.0f / (1.0f + expf(-acc));
        out[b] = sg * 0.2f - 0.1f;   // sigmoid * (OUT_MAX-OUT_MIN) + OUT_MIN
    }
}

extern "C" void kernel_launch(void* const* d_in, const int* in_sizes, int n_in,
                              void* d_out, int out_size) {
    const float* z       = (const float*)d_in[0];
    const float* weights = (const float*)d_in[1];
    const float* W1      = (const float*)d_in[2];
    const float* b1      = (const float*)d_in[3];
    const float* W2      = (const float*)d_in[4];
    const float* b2      = (const float*)d_in[5];
    const float* W3      = (const float*)d_in[6];
    const float* b3      = (const float*)d_in[7];
    float* out           = (float*)d_out;

    const int B = in_sizes[0] / NQ;   // 4096
    qgan_kernel<<<B, THREADS>>>(z, weights, W1, b1, W2, b2, W3, b3, out);
}

// round 2
// speedup vs baseline: 3.3182x; 3.3182x over previous
#include <cuda_runtime.h>
#include <math.h>

#define FULLM 0xffffffffu
#define NQ 10
#define NL 3
#define WPB 4                  // warps (samples) per block
#define THREADS (WPB * 32)

// --- gate on a register bit K (index bits 4..0) : pure FFMA -----------------
template<int K>
__device__ __forceinline__ void gate_reg(float sx[32], float sy[32],
                                         float2 v00, float2 v01,
                                         float2 v10, float2 v11) {
#pragma unroll
    for (int r = 0; r < 32; r++) {
        if (r & (1 << K)) continue;
        const int r1 = r | (1 << K);
        float a0x = sx[r],  a0y = sy[r];
        float a1x = sx[r1], a1y = sy[r1];
        sx[r]  = v00.x*a0x - v00.y*a0y + v01.x*a1x - v01.y*a1y;
        sy[r]  = v00.x*a0y + v00.y*a0x + v01.x*a1y + v01.y*a1x;
        sx[r1] = v10.x*a0x - v10.y*a0y + v11.x*a1x - v11.y*a1y;
        sy[r1] = v10.x*a0y + v10.y*a0x + v11.x*a1y + v11.y*a1x;
    }
}

// --- gate on a lane bit J (index bits 9..5) : shfl_xor + FFMA ---------------
template<int J>
__device__ __forceinline__ void gate_lane(float sx[32], float sy[32], int lane,
                                          float2 v00, float2 v01,
                                          float2 v10, float2 v11) {
    const bool hi = (lane >> J) & 1;
    const float2 c1 = hi ? v11 : v00;   // coeff on my amplitude
    const float2 c2 = hi ? v10 : v01;   // coeff on partner amplitude
#pragma unroll
    for (int r = 0; r < 32; r++) {
        float ox = __shfl_xor_sync(FULLM, sx[r], 1 << J);
        float oy = __shfl_xor_sync(FULLM, sy[r], 1 << J);
        float mx = sx[r], my = sy[r];
        sx[r] = c1.x*mx - c1.y*my + c2.x*ox - c2.y*oy;
        sy[r] = c1.x*my + c1.y*mx + c2.x*oy + c2.y*ox;
    }
}

// wire W acts on index bit k = 9-W. k>=5 -> lane bit (k-5), else register bit k.
template<int W>
__device__ __forceinline__ void apply_wire(float sx[32], float sy[32], int lane,
                                           float2 v00, float2 v01,
                                           float2 v10, float2 v11) {
    if constexpr (W < 5) gate_lane<4 - W>(sx, sy, lane, v00, v01, v10, v11);
    else                 gate_reg<9 - W>(sx, sy, v00, v01, v10, v11);
}

// --- fused CNOT chain (ctrl k=9..1, tgt k-1): t_k = XOR_{j>=k} s_j ----------
// Gather form: new[t] = old[s], s_k = t_k ^ t_{k+1}.
// src lane = lane ^ (lane>>1); src reg = (r ^ (r>>1)) ^ (parity(lane)<<4).
// Supplier pre-swaps reg halves if parity(own lane) so the supplied register
// index is the compile-time constant r^(r>>1).
__device__ __forceinline__ void cnot_perm(float sx[32], float sy[32], int lane) {
    const int  srcLane = (lane ^ (lane >> 1)) & 31;
    const bool ps = __popc(lane) & 1;
#pragma unroll
    for (int r = 0; r < 16; r++) {
        float ax = sx[r], bx = sx[r + 16];
        sx[r] = ps ? bx : ax;  sx[r + 16] = ps ? ax : bx;
        float ay = sy[r], by = sy[r + 16];
        sy[r] = ps ? by : ay;  sy[r + 16] = ps ? ay : by;
    }
    float nx[32], ny[32];
#pragma unroll
    for (int r = 0; r < 32; r++) {
        const int s0 = r ^ (r >> 1);
        nx[r] = __shfl_sync(FULLM, sx[s0], srcLane);
        ny[r] = __shfl_sync(FULLM, sy[s0], srcLane);
    }
#pragma unroll
    for (int r = 0; r < 32; r++) { sx[r] = nx[r]; sy[r] = ny[r]; }
}

__global__ __launch_bounds__(THREADS)
void qgan_kernel(const float* __restrict__ z,       // [B,10]
                 const float* __restrict__ weights, // [3,10,3]
                 const float* __restrict__ W1, const float* __restrict__ b1,
                 const float* __restrict__ W2, const float* __restrict__ b2,
                 const float* __restrict__ W3, const float* __restrict__ b3,
                 float* __restrict__ out, int B)
{
    __shared__ float2 Us[NL * NQ * 4];   // 30 unitaries, shared by all samples

    const int tid  = threadIdx.x;
    const int lane = tid & 31;
    const int wix  = tid >> 5;
    const int b    = blockIdx.x * WPB + wix;

    // Build U[l][i] once per block: U = Rz(c) Ry(b) Rz(a)
    if (tid < NL * NQ) {
        float a  = weights[tid * 3 + 0];
        float bb = weights[tid * 3 + 1];
        float c  = weights[tid * 3 + 2];
        float cb, sb;  __sincosf(0.5f * bb, &sb, &cb);
        float capc, sapc, camc, samc;
        __sincosf(0.5f * (a + c), &sapc, &capc);
        __sincosf(0.5f * (a - c), &samc, &camc);
        Us[tid * 4 + 0] = make_float2( cb * capc, -cb * sapc);
        Us[tid * 4 + 1] = make_float2(-sb * camc, -sb * samc);
        Us[tid * 4 + 2] = make_float2( sb * camc, -sb * samc);
        Us[tid * 4 + 3] = make_float2( cb * capc,  cb * sapc);
    }
    __syncthreads();

    if (b < B) {
        // RY half-angle cos/sin per wire (wire = lane, lanes 0..9)
        float zc = 1.0f, zs = 0.0f;
        if (lane < NQ) {
            float zv = z[b * NQ + lane];
            zv = fminf(fmaxf(zv, -1.0f), 1.0f);
            __sincosf(0.5f * zv, &zs, &zc);
        }

        // state registers: index = (lane<<5) | r
        float sx[32], sy[32];
#pragma unroll
        for (int r = 0; r < 32; r++) { sx[r] = 0.0f; sy[r] = 0.0f; }
        sx[0] = (lane == 0) ? 1.0f : 0.0f;

#pragma unroll 1
        for (int l = 0; l < NL; l++) {
            const float2* Ub = &Us[l * NQ * 4];

#define DO_WIRE(W) {                                                          \
            float2 u00 = Ub[4*(W)+0], u01 = Ub[4*(W)+1];                      \
            float2 u10 = Ub[4*(W)+2], u11 = Ub[4*(W)+3];                      \
            if (l == 0) {  /* fuse V = U * RY(wire W) */                      \
                float c = __shfl_sync(FULLM, zc, (W));                        \
                float s = __shfl_sync(FULLM, zs, (W));                        \
                float2 t00 = make_float2(u00.x*c + u01.x*s, u00.y*c + u01.y*s);\
                float2 t01 = make_float2(u01.x*c - u00.x*s, u01.y*c - u00.y*s);\
                float2 t10 = make_float2(u10.x*c + u11.x*s, u10.y*c + u11.y*s);\
                float2 t11 = make_float2(u11.x*c - u10.x*s, u11.y*c - u10.y*s);\
                apply_wire<(W)>(sx, sy, lane, t00, t01, t10, t11);            \
            } else {                                                          \
                apply_wire<(W)>(sx, sy, lane, u00, u01, u10, u11);            \
            } }

            DO_WIRE(0) DO_WIRE(1) DO_WIRE(2) DO_WIRE(3) DO_WIRE(4)
            DO_WIRE(5) DO_WIRE(6) DO_WIRE(7) DO_WIRE(8) DO_WIRE(9)
#undef DO_WIRE

            if (l < NL - 1) cnot_perm(sx, sy, lane);
            // last layer's CNOT chain is folded into the feature signs below
        }

        // --- features, with permutation folded into the signs ---------------
        // true index t of stored slot s: t_k = XOR_{j>=k} s_j
        float acc[5] = {0, 0, 0, 0, 0};   // signed sums for bits k=0..4 (sign parity(r>>k))
        float ptot = 0.0f;
#pragma unroll
        for (int r = 0; r < 32; r++) {
            float p = sx[r]*sx[r] + sy[r]*sy[r];
            ptot += p;
#pragma unroll
            for (int k = 0; k < 5; k++)
                acc[k] += (__popc(r >> k) & 1) ? -p : p;
        }
        const int pl = __popc(lane) & 1;
        float g[NQ];
#pragma unroll
        for (int i = 0; i < 5; i++) {          // wire i -> bit 9-i, sign parity(lane>>(4-i))
            int sgn = __popc(lane >> (4 - i)) & 1;
            g[i] = sgn ? -ptot : ptot;
        }
#pragma unroll
        for (int i = 5; i < NQ; i++)           // wire i -> bit 9-i, extra parity(lane) factor
            g[i] = pl ? -acc[9 - i] : acc[9 - i];

#pragma unroll
        for (int i = 0; i < NQ; i++) {
#pragma unroll
            for (int o = 16; o > 0; o >>= 1)
                g[i] += __shfl_xor_sync(FULLM, g[i], o);
        }

        // --- MLP 10 -> 32 -> 16 -> 1 (warp-local) ---------------------------
        float a1 = b1[lane];
#pragma unroll
        for (int i = 0; i < NQ; i++) a1 += g[i] * W1[i * 32 + lane];
        float h1v = tanhf(a1);

        float a2 = b2[lane & 15];
#pragma unroll
        for (int i = 0; i < 32; i++) {
            float h = __shfl_sync(FULLM, h1v, i);
            a2 += h * W2[i * 16 + (lane & 15)];
        }
        float h2v = tanhf(a2);

        float a3 = b3[0];
#pragma unroll
        for (int i = 0; i < 16; i++)
            a3 += __shfl_sync(FULLM, h2v, i) * W3[i];

        if (lane == 0) {
            float sg = 1.0f / (1.0f + expf(-a3));
            out[b] = sg * 0.2f - 0.1f;
        }
    }
}

extern "C" void kernel_launch(void* const* d_in, const int* in_sizes, int n_in,
                              void* d_out, int out_size) {
    const float* z       = (const float*)d_in[0];
    const float* weights = (const float*)d_in[1];
    const float* W1      = (const float*)d_in[2];
    const float* b1      = (const float*)d_in[3];
    const float* W2      = (const float*)d_in[4];
    const float* b2      = (const float*)d_in[5];
    const float* W3      = (const float*)d_in[6];
    const float* b3      = (const float*)d_in[7];
    float* out           = (float*)d_out;

    const int B = in_sizes[0] / NQ;     // 4096
    const int grid = (B + WPB - 1) / WPB;
    qgan_kernel<<<grid, THREADS>>>(z, weights, W1, b1, W2, b2, W3, b3, out, B);
}

// round 3
// speedup vs baseline: 3.9851x; 1.2010x over previous
#include <cuda_runtime.h>
#include <math.h>

#define FULLM 0xffffffffu
#define NQ 10
#define NL 3
#define WPB 4
#define THREADS (WPB * 32)

typedef unsigned long long u64;

// ---- f32x2 packed helpers (sm_100+) ----------------------------------------
__device__ __forceinline__ u64 bc2(float s) {
    u64 d; unsigned r = __float_as_uint(s);
    asm("mov.b64 %0, {%1, %1};" : "=l"(d) : "r"(r));
    return d;
}
__device__ __forceinline__ u64 pk2(float lo, float hi) {
    u64 d; unsigned a = __float_as_uint(lo), b = __float_as_uint(hi);
    asm("mov.b64 %0, {%1, %2};" : "=l"(d) : "r"(a), "r"(b));
    return d;
}
__device__ __forceinline__ void up2(u64 a, float& lo, float& hi) {
    unsigned l, h;
    asm("mov.b64 {%0, %1}, %2;" : "=r"(l), "=r"(h) : "l"(a));
    lo = __uint_as_float(l); hi = __uint_as_float(h);
}
__device__ __forceinline__ u64 fma2(u64 a, u64 b, u64 c) {
    u64 d;
    asm("fma.rn.f32x2 %0, %1, %2, %3;" : "=l"(d) : "l"(a), "l"(b), "l"(c));
    return d;
}
__device__ __forceinline__ u64 mul2(u64 a, u64 b) {
    u64 d;
    asm("mul.rn.f32x2 %0, %1, %2;" : "=l"(d) : "l"(a), "l"(b));
    return d;
}
__device__ __forceinline__ u64 add2(u64 a, u64 b) {
    u64 d;
    asm("add.rn.f32x2 %0, %1, %2;" : "=l"(d) : "l"(a), "l"(b));
    return d;
}
__device__ __forceinline__ u64 swp2(u64 a) {
    unsigned l, h;
    asm("mov.b64 {%0, %1}, %2;" : "=r"(l), "=r"(h) : "l"(a));
    u64 d;
    asm("mov.b64 %0, {%1, %2};" : "=l"(d) : "r"(h), "r"(l));
    return d;
}
__device__ __forceinline__ u64 shflx2(u64 a, int mask) {
    unsigned l, h;
    asm("mov.b64 {%0, %1}, %2;" : "=r"(l), "=r"(h) : "l"(a));
    l = __shfl_xor_sync(FULLM, l, mask);
    h = __shfl_xor_sync(FULLM, h, mask);
    u64 d;
    asm("mov.b64 %0, {%1, %2};" : "=l"(d) : "r"(l), "r"(h));
    return d;
}
__device__ __forceinline__ u64 shfli2(u64 a, int src) {
    unsigned l, h;
    asm("mov.b64 {%0, %1}, %2;" : "=r"(l), "=r"(h) : "l"(a));
    l = __shfl_sync(FULLM, l, src);
    h = __shfl_sync(FULLM, h, src);
    u64 d;
    asm("mov.b64 %0, {%1, %2};" : "=l"(d) : "r"(l), "r"(h));
    return d;
}

// state: amplitude index = (lane<<5) | (m<<1) | h ; pX/pY hold (h=0, h=1) packed.
// wire W acts on index bit k = 9-W. k>=5: lane bit (k-5); k in 1..4: m bit k-1;
// k==0: intra-pair.
template<int W>
__device__ __forceinline__ void apply_wire(u64 pX[16], u64 pY[16], int lane,
                                           float2 u00, float2 u01,
                                           float2 u10, float2 u11) {
    if constexpr (W < 5) {
        const int J = 4 - W;
        const bool hi = (lane >> J) & 1;
        float2 c1 = hi ? u11 : u00;
        float2 c2 = hi ? u10 : u01;
        u64 b1x = bc2(c1.x), b1y = bc2(c1.y), b1n = bc2(-c1.y);
        u64 b2x = bc2(c2.x), b2y = bc2(c2.y), b2n = bc2(-c2.y);
#pragma unroll
        for (int m = 0; m < 16; m++) {
            u64 ox = shflx2(pX[m], 1 << J);
            u64 oy = shflx2(pY[m], 1 << J);
            u64 nx = fma2(b1x, pX[m], fma2(b1n, pY[m], fma2(b2x, ox, mul2(b2n, oy))));
            u64 ny = fma2(b1y, pX[m], fma2(b1x, pY[m], fma2(b2y, ox, mul2(b2x, oy))));
            pX[m] = nx; pY[m] = ny;
        }
    } else if constexpr (W < 9) {
        const int Kb = 8 - W;     // m-bit
        u64 x00 = bc2(u00.x), y00 = bc2(u00.y), n00 = bc2(-u00.y);
        u64 x01 = bc2(u01.x), y01 = bc2(u01.y), n01 = bc2(-u01.y);
        u64 x10 = bc2(u10.x), y10 = bc2(u10.y), n10 = bc2(-u10.y);
        u64 x11 = bc2(u11.x), y11 = bc2(u11.y), n11 = bc2(-u11.y);
#pragma unroll
        for (int m0 = 0; m0 < 16; m0++) {
            if (m0 & (1 << Kb)) continue;
            const int m1 = m0 | (1 << Kb);
            u64 px0 = pX[m0], py0 = pY[m0], px1 = pX[m1], py1 = pY[m1];
            pX[m0] = fma2(x00, px0, fma2(n00, py0, fma2(x01, px1, mul2(n01, py1))));
            pY[m0] = fma2(y00, px0, fma2(x00, py0, fma2(y01, px1, mul2(x01, py1))));
            pX[m1] = fma2(x10, px0, fma2(n10, py0, fma2(x11, px1, mul2(n11, py1))));
            pY[m1] = fma2(y10, px0, fma2(x10, py0, fma2(y11, px1, mul2(x11, py1))));
        }
    } else {  // W == 9: intra-pair gate on bit 0
        u64 xd = pk2(u00.x, u11.x), xo = pk2(u01.x, u10.x);
        u64 yd = pk2(u00.y, u11.y), yo = pk2(u01.y, u10.y);
        u64 nd = pk2(-u00.y, -u11.y), no = pk2(-u01.y, -u10.y);
#pragma unroll
        for (int m = 0; m < 16; m++) {
            u64 sx = swp2(pX[m]), sy = swp2(pY[m]);
            u64 nx = fma2(xd, pX[m], fma2(nd, pY[m], fma2(xo, sx, mul2(no, sy))));
            u64 ny = fma2(yd, pX[m], fma2(xd, pY[m], fma2(yo, sx, mul2(xo, sy))));
            pX[m] = nx; pY[m] = ny;
        }
    }
}

// fused CNOT chain: stored slot s supplies true index t, t_k = XOR_{j>=k} s_j.
// gather: new[r] = old[r ^ (r>>1)] with lane source lane^(lane>>1) and
// supplier-side half-swap by own lane parity (bit4 of source reg index).
__device__ __forceinline__ void cnot_perm(u64 pX[16], u64 pY[16], int lane) {
    const int  srcLane = (lane ^ (lane >> 1)) & 31;
    const bool ps = __popc(lane) & 1;
#pragma unroll
    for (int m = 0; m < 8; m++) {
        u64 a = pX[m], b = pX[m + 8];
        pX[m] = ps ? b : a;  pX[m + 8] = ps ? a : b;
        u64 c = pY[m], d = pY[m + 8];
        pY[m] = ps ? d : c;  pY[m + 8] = ps ? c : d;
    }
    u64 nX[16], nY[16];
#pragma unroll
    for (int m = 0; m < 16; m++) {
        const int sm = m ^ (m >> 1);       // packed source slot
        u64 gx = shfli2(pX[sm], srcLane);
        u64 gy = shfli2(pY[sm], srcLane);
        if (m & 1) { gx = swp2(gx); gy = swp2(gy); }   // odd m: halves swapped
        nX[m] = gx; nY[m] = gy;
    }
#pragma unroll
    for (int m = 0; m < 16; m++) { pX[m] = nX[m]; pY[m] = nY[m]; }
}

__global__ __launch_bounds__(THREADS)
void qgan_kernel(const float* __restrict__ z,
                 const float* __restrict__ weights,
                 const float* __restrict__ W1, const float* __restrict__ b1,
                 const float* __restrict__ W2, const float* __restrict__ b2,
                 const float* __restrict__ W3, const float* __restrict__ b3,
                 float* __restrict__ out, int B)
{
    __shared__ float2 Us[NL * NQ * 4];

    const int tid  = threadIdx.x;
    const int lane = tid & 31;
    const int wix  = tid >> 5;
    const int b    = blockIdx.x * WPB + wix;

    if (tid < NL * NQ) {
        float a  = weights[tid * 3 + 0];
        float bb = weights[tid * 3 + 1];
        float c  = weights[tid * 3 + 2];
        float cb, sb;  __sincosf(0.5f * bb, &sb, &cb);
        float capc, sapc, camc, samc;
        __sincosf(0.5f * (a + c), &sapc, &capc);
        __sincosf(0.5f * (a - c), &samc, &camc);
        Us[tid * 4 + 0] = make_float2( cb * capc, -cb * sapc);
        Us[tid * 4 + 1] = make_float2(-sb * camc, -sb * samc);
        Us[tid * 4 + 2] = make_float2( sb * camc, -sb * samc);
        Us[tid * 4 + 3] = make_float2( cb * capc,  cb * sapc);
    }
    __syncthreads();

    if (b < B) {
        float zc = 1.0f, zs = 0.0f;
        if (lane < NQ) {
            float zv = z[b * NQ + lane];
            zv = fminf(fmaxf(zv, -1.0f), 1.0f);
            __sincosf(0.5f * zv, &zs, &zc);
        }

        u64 pX[16], pY[16];
        const u64 Z64 = bc2(0.0f);
#pragma unroll
        for (int m = 0; m < 16; m++) { pX[m] = Z64; pY[m] = Z64; }
        pX[0] = pk2(lane == 0 ? 1.0f : 0.0f, 0.0f);

#pragma unroll 1
        for (int l = 0; l < NL; l++) {
            const float2* Ub = &Us[l * NQ * 4];

#define DO_WIRE(W) {                                                           \
            float2 u00 = Ub[4*(W)+0], u01 = Ub[4*(W)+1];                       \
            float2 u10 = Ub[4*(W)+2], u11 = Ub[4*(W)+3];                       \
            if (l == 0) {  /* V = U * RY(wire W) */                            \
                float c = __shfl_sync(FULLM, zc, (W));                         \
                float s = __shfl_sync(FULLM, zs, (W));                         \
                float2 t00 = make_float2(u00.x*c + u01.x*s, u00.y*c + u01.y*s);\
                float2 t01 = make_float2(u01.x*c - u00.x*s, u01.y*c - u00.y*s);\
                float2 t10 = make_float2(u10.x*c + u11.x*s, u10.y*c + u11.y*s);\
                float2 t11 = make_float2(u11.x*c - u10.x*s, u11.y*c - u10.y*s);\
                apply_wire<(W)>(pX, pY, lane, t00, t01, t10, t11);             \
            } else {                                                           \
                apply_wire<(W)>(pX, pY, lane, u00, u01, u10, u11);             \
            } }

            DO_WIRE(0) DO_WIRE(1) DO_WIRE(2) DO_WIRE(3) DO_WIRE(4)
            DO_WIRE(5) DO_WIRE(6) DO_WIRE(7) DO_WIRE(8) DO_WIRE(9)
#undef DO_WIRE

            if (l < NL - 1) cnot_perm(pX, pY, lane);
        }

        // --- features (last CNOT chain folded into signs) --------------------
        u64 ptotP = Z64, a0P = Z64, aP1 = Z64, aP2 = Z64, aP3 = Z64, aP4 = Z64;
        const u64 bN1 = bc2(-1.0f);
#pragma unroll
        for (int m = 0; m < 16; m++) {
            u64 pp = fma2(pX[m], pX[m], mul2(pY[m], pY[m]));
            ptotP = add2(ptotP, pp);
            a0P = (__popc(m) & 1)        ? fma2(pp, bN1, a0P) : add2(a0P, pp);
            aP1 = (__popc(m >> 0) & 1)   ? fma2(pp, bN1, aP1) : add2(aP1, pp);
            aP2 = (__popc(m >> 1) & 1)   ? fma2(pp, bN1, aP2) : add2(aP2, pp);
            aP3 = (__popc(m >> 2) & 1)   ? fma2(pp, bN1, aP3) : add2(aP3, pp);
            aP4 = (__popc(m >> 3) & 1)   ? fma2(pp, bN1, aP4) : add2(aP4, pp);
        }
        float lo, hi, ptot, A[5];
        up2(ptotP, lo, hi);  ptot = lo + hi;
        up2(a0P,   lo, hi);  A[0] = lo - hi;   // bit0 sign flips between halves
        up2(aP1,   lo, hi);  A[1] = lo + hi;
        up2(aP2,   lo, hi);  A[2] = lo + hi;
        up2(aP3,   lo, hi);  A[3] = lo + hi;
        up2(aP4,   lo, hi);  A[4] = lo + hi;

        const int pl = __popc(lane) & 1;
        float g[NQ];
#pragma unroll
        for (int i = 0; i < 5; i++) {
            int sgn = __popc(lane >> (4 - i)) & 1;
            g[i] = sgn ? -ptot : ptot;
        }
#pragma unroll
        for (int i = 5; i < NQ; i++)
            g[i] = pl ? -A[9 - i] : A[9 - i];

#pragma unroll
        for (int i = 0; i < NQ; i++) {
#pragma unroll
            for (int o = 16; o > 0; o >>= 1)
                g[i] += __shfl_xor_sync(FULLM, g[i], o);
        }

        // --- MLP 10 -> 32 -> 16 -> 1 ----------------------------------------
        float a1 = b1[lane];
#pragma unroll
        for (int i = 0; i < NQ; i++) a1 += g[i] * W1[i * 32 + lane];
        float h1v = tanhf(a1);

        float a2 = b2[lane & 15];
#pragma unroll
        for (int i = 0; i < 32; i++) {
            float h = __shfl_sync(FULLM, h1v, i);
            a2 += h * W2[i * 16 + (lane & 15)];
        }
        float h2v = tanhf(a2);

        float a3 = b3[0];
#pragma unroll
        for (int i = 0; i < 16; i++)
            a3 += __shfl_sync(FULLM, h2v, i) * W3[i];

        if (lane == 0) {
            float sg = 1.0f / (1.0f + expf(-a3));
            out[b] = sg * 0.2f - 0.1f;
        }
    }
}

extern "C" void kernel_launch(void* const* d_in, const int* in_sizes, int n_in,
                              void* d_out, int out_size) {
    const float* z       = (const float*)d_in[0];
    const float* weights = (const float*)d_in[1];
    const float* W1      = (const float*)d_in[2];
    const float* b1      = (const float*)d_in[3];
    const float* W2      = (const float*)d_in[4];
    const float* b2      = (const float*)d_in[5];
    const float* W3      = (const float*)d_in[6];
    const float* b3      = (const float*)d_in[7];
    float* out           = (float*)d_out;

    const int B = in_sizes[0] / NQ;
    const int grid = (B + WPB - 1) / WPB;
    qgan_kernel<<<grid, THREADS>>>(z, weights, W1, b1, W2, b2, W3, b3, out, B);
}

// round 4
// speedup vs baseline: 4.7235x; 1.1853x over previous
#include <cuda_runtime.h>
#include <math.h>

#define FULLM 0xffffffffu
#define NQ 10
#define WPB 4
#define THREADS (WPB * 32)

typedef unsigned long long u64;

// ---- f32x2 packed helpers --------------------------------------------------
__device__ __forceinline__ u64 bc2(float s) {
    u64 d; unsigned r = __float_as_uint(s);
    asm("mov.b64 %0, {%1, %1};" : "=l"(d) : "r"(r));
    return d;
}
__device__ __forceinline__ u64 pk2(float lo, float hi) {
    u64 d; unsigned a = __float_as_uint(lo), b = __float_as_uint(hi);
    asm("mov.b64 %0, {%1, %2};" : "=l"(d) : "r"(a), "r"(b));
    return d;
}
__device__ __forceinline__ void up2(u64 a, float& lo, float& hi) {
    unsigned l, h;
    asm("mov.b64 {%0, %1}, %2;" : "=r"(l), "=r"(h) : "l"(a));
    lo = __uint_as_float(l); hi = __uint_as_float(h);
}
__device__ __forceinline__ u64 fma2(u64 a, u64 b, u64 c) {
    u64 d;
    asm("fma.rn.f32x2 %0, %1, %2, %3;" : "=l"(d) : "l"(a), "l"(b), "l"(c));
    return d;
}
__device__ __forceinline__ u64 mul2(u64 a, u64 b) {
    u64 d;
    asm("mul.rn.f32x2 %0, %1, %2;" : "=l"(d) : "l"(a), "l"(b));
    return d;
}
__device__ __forceinline__ u64 add2(u64 a, u64 b) {
    u64 d;
    asm("add.rn.f32x2 %0, %1, %2;" : "=l"(d) : "l"(a), "l"(b));
    return d;
}
__device__ __forceinline__ u64 swp2(u64 a) {
    unsigned l, h;
    asm("mov.b64 {%0, %1}, %2;" : "=r"(l), "=r"(h) : "l"(a));
    u64 d;
    asm("mov.b64 %0, {%1, %2};" : "=l"(d) : "r"(h), "r"(l));
    return d;
}
__device__ __forceinline__ u64 shflx2(u64 a, int mask) {
    unsigned l, h;
    asm("mov.b64 {%0, %1}, %2;" : "=r"(l), "=r"(h) : "l"(a));
    l = __shfl_xor_sync(FULLM, l, mask);
    h = __shfl_xor_sync(FULLM, h, mask);
    u64 d;
    asm("mov.b64 %0, {%1, %2};" : "=l"(d) : "r"(l), "r"(h));
    return d;
}

// complex coefficient broadcast
struct CB { u64 x, y, yn; };
__device__ __forceinline__ CB mkcb(float2 c) {
    CB r; r.x = bc2(c.x); r.y = bc2(c.y); r.yn = bc2(-c.y); return r;
}
// n = c1*a + c2*b  (complex, packed)
__device__ __forceinline__ void ccomb(u64 ax, u64 ay, u64 bx, u64 by,
                                      const CB& c1, const CB& c2,
                                      u64& nx, u64& ny) {
    nx = fma2(c1.x, ax, fma2(c1.yn, ay, fma2(c2.x, bx, mul2(c2.yn, by))));
    ny = fma2(c1.y, ax, fma2(c1.x, ay, fma2(c2.y, bx, mul2(c2.x, by))));
}

// ---- gate primitives -------------------------------------------------------
// State layout: amp index s = (lane<<5)|(m<<1)|h ; pX/pY hold (h=0,h=1) packed.

// gate pairing across lanes only (xorMask on lane); hi = this thread holds row1
__device__ __forceinline__ void lane_gate(u64 pX[16], u64 pY[16],
                                          int xorMask, bool hi,
                                          float2 u00, float2 u01,
                                          float2 u10, float2 u11) {
    CB c1 = mkcb(hi ? u11 : u00), c2 = mkcb(hi ? u10 : u01);
#pragma unroll
    for (int m = 0; m < 16; m++) {
        u64 bx = shflx2(pX[m], xorMask), by = shflx2(pY[m], xorMask);
        u64 nx, ny; ccomb(pX[m], pY[m], bx, by, c1, c2, nx, ny);
        pX[m] = nx; pY[m] = ny;
    }
}

// gate pairing across lane xor LX AND register slot m xor MXOR (single-bit MXOR)
template<int MXOR>
__device__ __forceinline__ void cross_gate(u64 pX[16], u64 pY[16],
                                           int laneXor, bool hi,
                                           float2 u00, float2 u01,
                                           float2 u10, float2 u11) {
    CB c1 = mkcb(hi ? u11 : u00), c2 = mkcb(hi ? u10 : u01);
#pragma unroll
    for (int m0 = 0; m0 < 16; m0++) {
        if (m0 & MXOR) continue;
        const int m1 = m0 | MXOR;
        u64 b0x = shflx2(pX[m1], laneXor), b0y = shflx2(pY[m1], laneXor);
        u64 b1x = shflx2(pX[m0], laneXor), b1y = shflx2(pY[m0], laneXor);
        u64 n0x, n0y, n1x, n1y;
        ccomb(pX[m0], pY[m0], b0x, b0y, c1, c2, n0x, n0y);
        ccomb(pX[m1], pY[m1], b1x, b1y, c1, c2, n1x, n1y);
        pX[m0] = n0x; pY[m0] = n0y; pX[m1] = n1x; pY[m1] = n1y;
    }
}

template<int MXOR> struct Anch {
    static const int v = (MXOR >= 8) ? 8 : (MXOR >= 4) ? 4 : (MXOR >= 2) ? 2 : 1;
};

// register-pair gate, pairing m ^ MXOR; per-pair role swap = sb ^ parity(mA & CLS)
template<int MXOR, int CLS>
__device__ __forceinline__ void reg_gate(u64 pX[16], u64 pY[16], bool sb,
                                         float2 u00, float2 u01,
                                         float2 u10, float2 u11) {
    const float2 v00 = sb ? u11 : u00, v01 = sb ? u10 : u01;
    const float2 v10 = sb ? u01 : u10, v11 = sb ? u00 : u11;
    CB a00 = mkcb(v00), a01 = mkcb(v01), a10 = mkcb(v10), a11 = mkcb(v11);
#pragma unroll
    for (int mA = 0; mA < 16; mA++) {
        if (mA & Anch<MXOR>::v) continue;
        const int mB = mA ^ MXOR;
        const bool cls = __popc(mA & CLS) & 1;
        const CB& q00 = cls ? a11 : a00;  const CB& q01 = cls ? a10 : a01;
        const CB& q10 = cls ? a01 : a10;  const CB& q11 = cls ? a00 : a11;
        u64 Ax = pX[mA], Ay = pY[mA], Bx = pX[mB], By = pY[mB];
        u64 nAx, nAy, nBx, nBy;
        ccomb(Ax, Ay, Bx, By, q00, q01, nAx, nAy);
        ccomb(Ax, Ay, Bx, By, q10, q11, nBx, nBy);
        pX[mA] = nAx; pY[mA] = nAy; pX[mB] = nBx; pY[mB] = nBy;
    }
}

// register-pair gate where partner also flips h: (m,h) <-> (m^MXOR, h^1)
template<int MXOR, int CLS>
__device__ __forceinline__ void hcross_gate(u64 pX[16], u64 pY[16], bool sb,
                                            float2 u00, float2 u01,
                                            float2 u10, float2 u11) {
    const float2 v00 = sb ? u11 : u00, v01 = sb ? u10 : u01;
    const float2 v10 = sb ? u01 : u10, v11 = sb ? u00 : u11;
    CB a00 = mkcb(v00), a01 = mkcb(v01), a10 = mkcb(v10), a11 = mkcb(v11);
#pragma unroll
    for (int mA = 0; mA < 16; mA++) {
        if (mA & Anch<MXOR>::v) continue;
        const int mB = mA ^ MXOR;
        const bool cls = __popc(mA & CLS) & 1;
        const CB& q00 = cls ? a11 : a00;  const CB& q01 = cls ? a10 : a01;
        const CB& q10 = cls ? a01 : a10;  const CB& q11 = cls ? a00 : a11;
        u64 Ax = pX[mA], Ay = pY[mA];
        u64 Bx = swp2(pX[mB]), By = swp2(pY[mB]);
        u64 nAx, nAy, nBx, nBy;
        ccomb(Ax, Ay, Bx, By, q00, q01, nAx, nAy);
        ccomb(Ax, Ay, Bx, By, q10, q11, nBx, nBy);
        pX[mA] = nAx; pY[mA] = nAy;
        pX[mB] = swp2(nBx); pY[mB] = swp2(nBy);
    }
}

// intra-pair (h) gate; per-m orientation swap = sb ^ parity(m & CLS)
template<int CLS>
__device__ __forceinline__ void pair_gate(u64 pX[16], u64 pY[16], bool sb,
                                          float2 u00, float2 u01,
                                          float2 u10, float2 u11) {
    const float2 d0 = sb ? u11 : u00, d1 = sb ? u00 : u11;
    const float2 o0 = sb ? u10 : u01, o1 = sb ? u01 : u10;
    u64 dxN = pk2(d0.x, d1.x), dyN = pk2(d0.y, d1.y), dnN = pk2(-d0.y, -d1.y);
    u64 oxN = pk2(o0.x, o1.x), oyN = pk2(o0.y, o1.y), onN = pk2(-o0.y, -o1.y);
    u64 dxS = swp2(dxN), dyS = swp2(dyN), dnS = swp2(dnN);
    u64 oxS = swp2(oxN), oyS = swp2(oyN), onS = swp2(onN);
#pragma unroll
    for (int m = 0; m < 16; m++) {
        const bool s = __popc(m & CLS) & 1;
        u64 dx = s ? dxS : dxN, dy = s ? dyS : dyN, dn = s ? dnS : dnN;
        u64 ox = s ? oxS : oxN, oy = s ? oyS : oyN, on = s ? onS : onN;
        u64 sx = swp2(pX[m]), sy = swp2(pY[m]);
        u64 nx = fma2(dx, pX[m], fma2(dn, pY[m], fma2(ox, sx, mul2(on, sy))));
        u64 ny = fma2(dy, pX[m], fma2(dx, pY[m], fma2(oy, sx, mul2(ox, sy))));
        pX[m] = nx; pY[m] = ny;
    }
}

__global__ __launch_bounds__(THREADS)
void qgan_kernel(const float* __restrict__ z,
                 const float* __restrict__ weights,
                 const float* __restrict__ W1, const float* __restrict__ b1,
                 const float* __restrict__ W2, const float* __restrict__ b2,
                 const float* __restrict__ W3, const float* __restrict__ b3,
                 float* __restrict__ out, int B)
{
    __shared__ float2 Us[3 * NQ * 4];

    const int tid  = threadIdx.x;
    const int lane = tid & 31;
    const int wix  = tid >> 5;
    const int b    = blockIdx.x * WPB + wix;

    if (tid < 3 * NQ) {
        float a  = weights[tid * 3 + 0];
        float bb = weights[tid * 3 + 1];
        float c  = weights[tid * 3 + 2];
        float cb, sb;  __sincosf(0.5f * bb, &sb, &cb);
        float capc, sapc, camc, samc;
        __sincosf(0.5f * (a + c), &sapc, &capc);
        __sincosf(0.5f * (a - c), &samc, &camc);
        Us[tid * 4 + 0] = make_float2( cb * capc, -cb * sapc);
        Us[tid * 4 + 1] = make_float2(-sb * camc, -sb * samc);
        Us[tid * 4 + 2] = make_float2( sb * camc, -sb * samc);
        Us[tid * 4 + 3] = make_float2( cb * capc,  cb * sapc);
    }
    __syncthreads();

    if (b >= B) return;

    float zc = 1.0f, zs = 0.0f;
    if (lane < NQ) {
        float zv = z[b * NQ + lane];
        zv = fminf(fmaxf(zv, -1.0f), 1.0f);
        __sincosf(0.5f * zv, &zs, &zc);
    }

    const bool pl  = __popc(lane) & 1;            // parity(lane)
    const bool pl2 = __popc(lane & 0b01010) & 1;  // parity(lane bits 1,3)
    const bool pl3 = __popc(lane & 0b10101) & 1;  // parity(lane bits 0,2,4)

    u64 pX[16], pY[16];
    const u64 Z64 = bc2(0.0f);
#pragma unroll
    for (int m = 0; m < 16; m++) { pX[m] = Z64; pY[m] = Z64; }
    pX[0] = pk2(lane == 0 ? 1.0f : 0.0f, 0.0f);

    // ======= layer 0: plain gates, RY fused in (V = U * RY(w)) =======
    {
        const float2* Ub = &Us[0];
#define FUSE(W, T00, T01, T10, T11)                                           \
        float2 T00, T01, T10, T11; {                                          \
            float2 u00 = Ub[4*(W)+0], u01 = Ub[4*(W)+1];                      \
            float2 u10 = Ub[4*(W)+2], u11 = Ub[4*(W)+3];                      \
            float c = __shfl_sync(FULLM, zc, (W));                            \
            float s = __shfl_sync(FULLM, zs, (W));                            \
            T00 = make_float2(u00.x*c + u01.x*s, u00.y*c + u01.y*s);          \
            T01 = make_float2(u01.x*c - u00.x*s, u01.y*c - u00.y*s);          \
            T10 = make_float2(u10.x*c + u11.x*s, u10.y*c + u11.y*s);          \
            T11 = make_float2(u11.x*c - u10.x*s, u11.y*c - u10.y*s); }

        { FUSE(0, t00, t01, t10, t11)
          lane_gate(pX, pY, 0b10000, (lane >> 4) & 1, t00, t01, t10, t11); }
        { FUSE(1, t00, t01, t10, t11)
          lane_gate(pX, pY, 0b01000, (lane >> 3) & 1, t00, t01, t10, t11); }
        { FUSE(2, t00, t01, t10, t11)
          lane_gate(pX, pY, 0b00100, (lane >> 2) & 1, t00, t01, t10, t11); }
        { FUSE(3, t00, t01, t10, t11)
          lane_gate(pX, pY, 0b00010, (lane >> 1) & 1, t00, t01, t10, t11); }
        { FUSE(4, t00, t01, t10, t11)
          lane_gate(pX, pY, 0b00001, lane & 1, t00, t01, t10, t11); }
        { FUSE(5, t00, t01, t10, t11)
          reg_gate<8, 0>(pX, pY, false, t00, t01, t10, t11); }
        { FUSE(6, t00, t01, t10, t11)
          reg_gate<4, 0>(pX, pY, false, t00, t01, t10, t11); }
        { FUSE(7, t00, t01, t10, t11)
          reg_gate<2, 0>(pX, pY, false, t00, t01, t10, t11); }
        { FUSE(8, t00, t01, t10, t11)
          reg_gate<1, 0>(pX, pY, false, t00, t01, t10, t11); }
        { FUSE(9, t00, t01, t10, t11)
          pair_gate<0>(pX, pY, false, t00, t01, t10, t11); }
#undef FUSE
    }

    // ======= layer 1: gates in once-permuted coords (mask e_k ^ e_{k-1}) =====
    {
        const float2* Ub = &Us[NQ * 4];
#define U4(W) Ub[4*(W)+0], Ub[4*(W)+1], Ub[4*(W)+2], Ub[4*(W)+3]
        lane_gate(pX, pY, 0b11000, (lane >> 4) & 1,                 U4(0));
        lane_gate(pX, pY, 0b01100, __popc(lane & 0b11000) & 1,      U4(1));
        lane_gate(pX, pY, 0b00110, __popc(lane & 0b11100) & 1,      U4(2));
        lane_gate(pX, pY, 0b00011, __popc(lane & 0b11110) & 1,      U4(3));
        cross_gate<8>(pX, pY, 0b00001, pl,                          U4(4));
        reg_gate<0b1100, 0b0000>(pX, pY, pl,                        U4(5));
        reg_gate<0b0110, 0b1000>(pX, pY, pl,                        U4(6));
        reg_gate<0b0011, 0b1100>(pX, pY, pl,                        U4(7));
        hcross_gate<1, 0b1110>(pX, pY, pl,                          U4(8));
        pair_gate<0b1111>(pX, pY, pl,                               U4(9));
#undef U4
    }

    // ======= layer 2: twice-permuted coords (mask e_k ^ e_{k-2}) =============
    {
        const float2* Ub = &Us[2 * NQ * 4];
#define U4(W) Ub[4*(W)+0], Ub[4*(W)+1], Ub[4*(W)+2], Ub[4*(W)+3]
        lane_gate(pX, pY, 0b10100, (lane >> 4) & 1,                 U4(0));
        lane_gate(pX, pY, 0b01010, (lane >> 3) & 1,                 U4(1));
        lane_gate(pX, pY, 0b00101, __popc(lane & 0b10100) & 1,      U4(2));
        cross_gate<8>(pX, pY, 0b00010, pl2,                         U4(3));
        cross_gate<4>(pX, pY, 0b00001, pl3,                         U4(4));
        reg_gate<0b1010, 0b0000>(pX, pY, pl2,                       U4(5));
        reg_gate<0b0101, 0b0000>(pX, pY, pl3,                       U4(6));
        hcross_gate<2, 0b1000>(pX, pY, pl2,                         U4(7));
        reg_gate<0b0001, 0b0100>(pX, pY, pl3,                       U4(8));
        pair_gate<0b1010>(pX, pY, pl2,                              U4(9));
#undef U4
    }

    // ======= features: fold M^3 (three perms) into signs =====================
    u64 pt = Z64, c4 = Z64, c3 = Z64, c2 = Z64, c1 = Z64, c0 = Z64;
    const u64 bN1 = bc2(-1.0f);
#pragma unroll
    for (int m = 0; m < 16; m++) {
        u64 pp = fma2(pX[m], pX[m], mul2(pY[m], pY[m]));
        pt = add2(pt, pp);
        c4 = ((m >> 3) & 1)             ? fma2(pp, bN1, c4) : add2(c4, pp);
        c3 = (__popc(m & 0b1100) & 1)   ? fma2(pp, bN1, c3) : add2(c3, pp);
        c2 = (__popc(m & 0b0110) & 1)   ? fma2(pp, bN1, c2) : add2(c2, pp);
        c1 = (__popc(m & 0b0011) & 1)   ? fma2(pp, bN1, c1) : add2(c1, pp);
        c0 = (__popc(m & 0b1001) & 1)   ? fma2(pp, bN1, c0) : add2(c0, pp);
    }
    float lo, hi, ptot, A5, A6, A7, A8, A9;
    up2(pt, lo, hi);  ptot = lo + hi;
    up2(c4, lo, hi);  A5 = lo + hi;
    up2(c3, lo, hi);  A6 = lo + hi;
    up2(c2, lo, hi);  A7 = lo + hi;
    up2(c1, lo, hi);  A8 = lo + hi;
    up2(c0, lo, hi);  A9 = lo - hi;     // bit0 (h) in mask -> opposite halves

    float g[NQ];
    g[0] = (__popc(lane & 0b10000) & 1) ? -ptot : ptot;
    g[1] = (__popc(lane & 0b11000) & 1) ? -ptot : ptot;
    g[2] = (__popc(lane & 0b01100) & 1) ? -ptot : ptot;
    g[3] = (__popc(lane & 0b00110) & 1) ? -ptot : ptot;
    g[4] = (__popc(lane & 0b10011) & 1) ? -ptot : ptot;
    g[5] = (__popc(lane & 0b11001) & 1) ? -A5 : A5;
    g[6] = (__popc(lane & 0b01100) & 1) ? -A6 : A6;
    g[7] = (__popc(lane & 0b00110) & 1) ? -A7 : A7;
    g[8] = (__popc(lane & 0b10011) & 1) ? -A8 : A8;
    g[9] = (__popc(lane & 0b11001) & 1) ? -A9 : A9;

#pragma unroll
    for (int i = 0; i < NQ; i++) {
#pragma unroll
        for (int o = 16; o > 0; o >>= 1)
            g[i] += __shfl_xor_sync(FULLM, g[i], o);
    }

    // ======= MLP 10 -> 32 -> 16 -> 1 =========================================
    float a1 = b1[lane];
#pragma unroll
    for (int i = 0; i < NQ; i++) a1 += g[i] * W1[i * 32 + lane];
    float h1v = tanhf(a1);

    float a2 = b2[lane & 15];
#pragma unroll
    for (int i = 0; i < 32; i++) {
        float h = __shfl_sync(FULLM, h1v, i);
        a2 += h * W2[i * 16 + (lane & 15)];
    }
    float h2v = tanhf(a2);

    float a3 = b3[0];
#pragma unroll
    for (int i = 0; i < 16; i++)
        a3 += __shfl_sync(FULLM, h2v, i) * W3[i];

    if (lane == 0) {
        float sg = 1.0f / (1.0f + expf(-a3));
        out[b] = sg * 0.2f - 0.1f;
    }
}

extern "C" void kernel_launch(void* const* d_in, const int* in_sizes, int n_in,
                              void* d_out, int out_size) {
    const float* z       = (const float*)d_in[0];
    const float* weights = (const float*)d_in[1];
    const float* W1      = (const float*)d_in[2];
    const float* b1      = (const float*)d_in[3];
    const float* W2      = (const float*)d_in[4];
    const float* b2      = (const float*)d_in[5];
    const float* W3      = (const float*)d_in[6];
    const float* b3      = (const float*)d_in[7];
    float* out           = (float*)d_out;

    const int B = in_sizes[0] / NQ;
    const int grid = (B + WPB - 1) / WPB;
    qgan_kernel<<<grid, THREADS>>>(z, weights, W1, b1, W2, b2, W3, b3, out, B);
}

// round 5
// speedup vs baseline: 5.8188x; 1.2319x over previous
#include <cuda_runtime.h>
#include <math.h>

#define FULLM 0xffffffffu
#define NQ 10
#define WPB 4
#define THREADS (WPB * 32)

typedef unsigned long long u64;

// ---- f32x2 packed helpers --------------------------------------------------
__device__ __forceinline__ u64 bc2(float s) {
    u64 d; unsigned r = __float_as_uint(s);
    asm("mov.b64 %0, {%1, %1};" : "=l"(d) : "r"(r));
    return d;
}
__device__ __forceinline__ u64 pk2(float lo, float hi) {
    u64 d; unsigned a = __float_as_uint(lo), b = __float_as_uint(hi);
    asm("mov.b64 %0, {%1, %2};" : "=l"(d) : "r"(a), "r"(b));
    return d;
}
__device__ __forceinline__ void up2(u64 a, float& lo, float& hi) {
    unsigned l, h;
    asm("mov.b64 {%0, %1}, %2;" : "=r"(l), "=r"(h) : "l"(a));
    lo = __uint_as_float(l); hi = __uint_as_float(h);
}
__device__ __forceinline__ u64 fma2(u64 a, u64 b, u64 c) {
    u64 d;
    asm("fma.rn.f32x2 %0, %1, %2, %3;" : "=l"(d) : "l"(a), "l"(b), "l"(c));
    return d;
}
__device__ __forceinline__ u64 mul2(u64 a, u64 b) {
    u64 d;
    asm("mul.rn.f32x2 %0, %1, %2;" : "=l"(d) : "l"(a), "l"(b));
    return d;
}
__device__ __forceinline__ u64 add2(u64 a, u64 b) {
    u64 d;
    asm("add.rn.f32x2 %0, %1, %2;" : "=l"(d) : "l"(a), "l"(b));
    return d;
}
__device__ __forceinline__ u64 swp2(u64 a) {
    unsigned l, h;
    asm("mov.b64 {%0, %1}, %2;" : "=r"(l), "=r"(h) : "l"(a));
    u64 d;
    asm("mov.b64 %0, {%1, %2};" : "=l"(d) : "r"(h), "r"(l));
    return d;
}
__device__ __forceinline__ u64 shflx2(u64 a, int mask) {
    unsigned l, h;
    asm("mov.b64 {%0, %1}, %2;" : "=r"(l), "=r"(h) : "l"(a));
    l = __shfl_xor_sync(FULLM, l, mask);
    h = __shfl_xor_sync(FULLM, h, mask);
    u64 d;
    asm("mov.b64 %0, {%1, %2};" : "=l"(d) : "r"(l), "r"(h));
    return d;
}

__device__ __forceinline__ float2 cmulf(float2 a, float2 b) {
    return make_float2(a.x * b.x - a.y * b.y, a.x * b.y + a.y * b.x);
}

struct CB { u64 x, y, yn; };
// n = c1*a + c2*b  (complex, packed)
__device__ __forceinline__ void ccomb(u64 ax, u64 ay, u64 bx, u64 by,
                                      const CB& c1, const CB& c2,
                                      u64& nx, u64& ny) {
    nx = fma2(c1.x, ax, fma2(c1.yn, ay, fma2(c2.x, bx, mul2(c2.yn, by))));
    ny = fma2(c1.y, ax, fma2(c1.x, ay, fma2(c2.y, bx, mul2(c2.x, by))));
}

// ---- gate primitives (SU(2): u10 = -conj(u01), u11 = conj(u00)) ------------
// State layout: amp index s = (lane<<5)|(m<<1)|h ; pX/pY hold (h=0,h=1) packed.

__device__ __forceinline__ void lane_gate(u64 pX[16], u64 pY[16],
                                          int xorMask, bool hi,
                                          float2 u00, float2 u01) {
    const float y0 = hi ? -u00.y : u00.y;
    const float x1 = hi ? -u01.x : u01.x;
    CB c1 { bc2(u00.x), bc2(y0), bc2(-y0) };
    CB c2 { bc2(x1), bc2(u01.y), bc2(-u01.y) };
#pragma unroll
    for (int m = 0; m < 16; m++) {
        u64 bx = shflx2(pX[m], xorMask), by = shflx2(pY[m], xorMask);
        u64 nx, ny; ccomb(pX[m], pY[m], bx, by, c1, c2, nx, ny);
        pX[m] = nx; pY[m] = ny;
    }
}

template<int MXOR>
__device__ __forceinline__ void cross_gate(u64 pX[16], u64 pY[16],
                                           int laneXor, bool hi,
                                           float2 u00, float2 u01) {
    const float y0 = hi ? -u00.y : u00.y;
    const float x1 = hi ? -u01.x : u01.x;
    CB c1 { bc2(u00.x), bc2(y0), bc2(-y0) };
    CB c2 { bc2(x1), bc2(u01.y), bc2(-u01.y) };
#pragma unroll
    for (int m0 = 0; m0 < 16; m0++) {
        if (m0 & MXOR) continue;
        const int m1 = m0 | MXOR;
        u64 b0x = shflx2(pX[m1], laneXor), b0y = shflx2(pY[m1], laneXor);
        u64 b1x = shflx2(pX[m0], laneXor), b1y = shflx2(pY[m0], laneXor);
        u64 n0x, n0y, n1x, n1y;
        ccomb(pX[m0], pY[m0], b0x, b0y, c1, c2, n0x, n0y);
        ccomb(pX[m1], pY[m1], b1x, b1y, c1, c2, n1x, n1y);
        pX[m0] = n0x; pY[m0] = n0y; pX[m1] = n1x; pY[m1] = n1y;
    }
}

template<int MXOR> struct Anch {
    static const int v = (MXOR >= 8) ? 8 : (MXOR >= 4) ? 4 : (MXOR >= 2) ? 2 : 1;
};

template<int MXOR, int CLS>
__device__ __forceinline__ void reg_gate(u64 pX[16], u64 pY[16], bool sb,
                                         float2 u00, float2 u01) {
    const float y0 = sb ? -u00.y : u00.y;
    const float x1 = sb ? -u01.x : u01.x;
    const u64 X0 = bc2(u00.x), Y0 = bc2(y0), Y0n = bc2(-y0);
    const u64 X1 = bc2(x1), X1n = bc2(-x1), Y1 = bc2(u01.y), Y1n = bc2(-u01.y);
    const CB q00 {X0, Y0, Y0n}, q01 {X1, Y1, Y1n};
    const CB q10 {X1n, Y1, Y1n}, q11 {X0, Y0n, Y0};
#pragma unroll
    for (int mA = 0; mA < 16; mA++) {
        if (mA & Anch<MXOR>::v) continue;
        const int mB = mA ^ MXOR;
        const bool cls = __popc(mA & CLS) & 1;
        const CB& c00 = cls ? q11 : q00;  const CB& c01 = cls ? q10 : q01;
        const CB& c10 = cls ? q01 : q10;  const CB& c11 = cls ? q00 : q11;
        u64 Ax = pX[mA], Ay = pY[mA], Bx = pX[mB], By = pY[mB];
        u64 nAx, nAy, nBx, nBy;
        ccomb(Ax, Ay, Bx, By, c00, c01, nAx, nAy);
        ccomb(Ax, Ay, Bx, By, c10, c11, nBx, nBy);
        pX[mA] = nAx; pY[mA] = nAy; pX[mB] = nBx; pY[mB] = nBy;
    }
}

template<int MXOR, int CLS>
__device__ __forceinline__ void hcross_gate(u64 pX[16], u64 pY[16], bool sb,
                                            float2 u00, float2 u01) {
    const float y0 = sb ? -u00.y : u00.y;
    const float x1 = sb ? -u01.x : u01.x;
    const u64 X0 = bc2(u00.x), Y0 = bc2(y0), Y0n = bc2(-y0);
    const u64 X1 = bc2(x1), X1n = bc2(-x1), Y1 = bc2(u01.y), Y1n = bc2(-u01.y);
    const CB q00 {X0, Y0, Y0n}, q01 {X1, Y1, Y1n};
    const CB q10 {X1n, Y1, Y1n}, q11 {X0, Y0n, Y0};
#pragma unroll
    for (int mA = 0; mA < 16; mA++) {
        if (mA & Anch<MXOR>::v) continue;
        const int mB = mA ^ MXOR;
        const bool cls = __popc(mA & CLS) & 1;
        const CB& c00 = cls ? q11 : q00;  const CB& c01 = cls ? q10 : q01;
        const CB& c10 = cls ? q01 : q10;  const CB& c11 = cls ? q00 : q11;
        u64 Ax = pX[mA], Ay = pY[mA];
        u64 Bx = swp2(pX[mB]), By = swp2(pY[mB]);
        u64 nAx, nAy, nBx, nBy;
        ccomb(Ax, Ay, Bx, By, c00, c01, nAx, nAy);
        ccomb(Ax, Ay, Bx, By, c10, c11, nBx, nBy);
        pX[mA] = nAx; pY[mA] = nAy;
        pX[mB] = swp2(nBx); pY[mB] = swp2(nBy);
    }
}

template<int CLS>
__device__ __forceinline__ void pair_gate(u64 pX[16], u64 pY[16], bool sb,
                                          float2 u00, float2 u01) {
    const float y0 = sb ? -u00.y : u00.y;
    const float x1 = sb ? -u01.x : u01.x;
    const u64 DX  = bc2(u00.x);
    const u64 DY  = pk2(y0, -y0), DN  = pk2(-y0, y0);
    const u64 OX  = pk2(x1, -x1), OXn = pk2(-x1, x1);
    const u64 OY  = bc2(u01.y),   ON  = bc2(-u01.y);
#pragma unroll
    for (int m = 0; m < 16; m++) {
        const bool s = __popc(m & CLS) & 1;
        u64 dy = s ? DN : DY, dn = s ? DY : DN, ox = s ? OXn : OX;
        u64 sx = swp2(pX[m]), sy = swp2(pY[m]);
        u64 nx = fma2(DX, pX[m], fma2(dn, pY[m], fma2(ox, sx, mul2(ON, sy))));
        u64 ny = fma2(dy, pX[m], fma2(DX, pY[m], fma2(OY, sx, mul2(ox, sy))));
        pX[m] = nx; pY[m] = ny;
    }
}

__global__ __launch_bounds__(THREADS)
void qgan_kernel(const float* __restrict__ z,
                 const float* __restrict__ weights,
                 const float* __restrict__ W1, const float* __restrict__ b1,
                 const float* __restrict__ W2, const float* __restrict__ b2,
                 const float* __restrict__ W3, const float* __restrict__ b3,
                 float* __restrict__ out, int B)
{
    __shared__ float4 Us[3 * NQ];   // (u00.x, u00.y, u01.x, u01.y) per gate

    const int tid  = threadIdx.x;
    const int lane = tid & 31;
    const int wix  = tid >> 5;
    const int b    = blockIdx.x * WPB + wix;

    if (tid < 3 * NQ) {
        float a  = weights[tid * 3 + 0];
        float bb = weights[tid * 3 + 1];
        float c  = weights[tid * 3 + 2];
        float cb, sb;  __sincosf(0.5f * bb, &sb, &cb);
        float capc, sapc, camc, samc;
        __sincosf(0.5f * (a + c), &sapc, &capc);
        __sincosf(0.5f * (a - c), &samc, &camc);
        // u00 = cb*(capc,-sapc), u01 = -sb*(camc,samc)
        Us[tid] = make_float4(cb * capc, -cb * sapc, -sb * camc, -sb * samc);
    }
    __syncthreads();

    if (b >= B) return;

    float zc = 1.0f, zs = 0.0f;
    if (lane < NQ) {
        float zv = z[b * NQ + lane];
        zv = fminf(fmaxf(zv, -1.0f), 1.0f);
        __sincosf(0.5f * zv, &zs, &zc);
    }

    const bool pl  = __popc(lane) & 1;
    const bool pl2 = __popc(lane & 0b01010) & 1;
    const bool pl3 = __popc(lane & 0b10101) & 1;

    u64 pX[16], pY[16];

    // ======= layer 0 on |0..0>: direct product-state construction ===========
    // col0 of V_w = U_w * RY_w:  A = u00*c + u01*s,  B = (u00.x*s - u01.x*c,
    //                                                     u01.y*c - u00.y*s)
    {
        float2 P = make_float2(1.0f, 0.0f);   // prefix over wires 0..4 (lane bits)
#pragma unroll
        for (int W = 0; W < 5; W++) {
            float4 u = Us[W];
            float c = __shfl_sync(FULLM, zc, W);
            float s = __shfl_sync(FULLM, zs, W);
            float2 A  = make_float2(u.x * c + u.z * s, u.y * c + u.w * s);
            float2 Bv = make_float2(u.x * s - u.z * c, u.w * c - u.y * s);
            float2 col = ((lane >> (4 - W)) & 1) ? Bv : A;
            P = cmulf(P, col);
        }
        float2 cA[5], cB[5];                 // wires 5..9
#pragma unroll
        for (int j = 0; j < 5; j++) {
            float4 u = Us[5 + j];
            float c = __shfl_sync(FULLM, zc, 5 + j);
            float s = __shfl_sync(FULLM, zs, 5 + j);
            cA[j] = make_float2(u.x * c + u.z * s, u.y * c + u.w * s);
            cB[j] = make_float2(u.x * s - u.z * c, u.w * c - u.y * s);
        }
        // wire 9 -> h (packed halves); fold wire 5 into two bases
        u64 Hx = pk2(cA[4].x, cB[4].x);
        u64 Hy = pk2(cA[4].y, cB[4].y);
        float2 P0 = cmulf(P, cA[0]);         // m bit3 = 0 (wire 5)
        float2 P1 = cmulf(P, cB[0]);         // m bit3 = 1
        u64 B0x = fma2(bc2(P0.x), Hx, mul2(bc2(-P0.y), Hy));
        u64 B0y = fma2(bc2(P0.x), Hy, mul2(bc2(P0.y),  Hx));
        u64 B1x = fma2(bc2(P1.x), Hx, mul2(bc2(-P1.y), Hy));
        u64 B1y = fma2(bc2(P1.x), Hy, mul2(bc2(P1.y),  Hx));
        // F over m bits 2..0 = wires 6,7,8
        float2 F[8];
        F[0] = make_float2(1.0f, 0.0f);
        F[1] = cA[3];                        // hmm: bit0 = wire 8
        // build: bit0 -> wire8 (cA[3]/cB[3]), bit1 -> wire7 (cA[2]/cB[2]),
        //        bit2 -> wire6 (cA[1]/cB[1])
        F[0] = cA[3];  F[1] = cB[3];
        {
            float2 G[4];
            G[0] = cmulf(cA[2], F[0]);  G[1] = cmulf(cA[2], F[1]);
            G[2] = cmulf(cB[2], F[0]);  G[3] = cmulf(cB[2], F[1]);
            F[0] = cmulf(cA[1], G[0]);  F[1] = cmulf(cA[1], G[1]);
            F[2] = cmulf(cA[1], G[2]);  F[3] = cmulf(cA[1], G[3]);
            F[4] = cmulf(cB[1], G[0]);  F[5] = cmulf(cB[1], G[1]);
            F[6] = cmulf(cB[1], G[2]);  F[7] = cmulf(cB[1], G[3]);
        }
#pragma unroll
        for (int m = 0; m < 16; m++) {
            // m bits: bit3=wire5 (base), bit2=wire6, bit1=wire7, bit0=wire8
            float2 f = F[((m & 4) ? 4 : 0) | ((m & 2) ? 2 : 0) | (m & 1)];
            u64 bx = (m & 8) ? B1x : B0x;
            u64 by = (m & 8) ? B1y : B0y;
            u64 fx = bc2(f.x), fy = bc2(f.y), fyn = bc2(-f.y);
            pX[m] = fma2(fx, bx, mul2(fyn, by));
            pY[m] = fma2(fx, by, mul2(fy, bx));
        }
    }

    // ======= layer 1: once-permuted coords (mask e_k ^ e_{k-1}) ==============
    {
        const float4* Ub = &Us[NQ];
#define U2(W) make_float2(Ub[(W)].x, Ub[(W)].y), make_float2(Ub[(W)].z, Ub[(W)].w)
        lane_gate(pX, pY, 0b11000, (lane >> 4) & 1,            U2(0));
        lane_gate(pX, pY, 0b01100, __popc(lane & 0b11000) & 1, U2(1));
        lane_gate(pX, pY, 0b00110, __popc(lane & 0b11100) & 1, U2(2));
        lane_gate(pX, pY, 0b00011, __popc(lane & 0b11110) & 1, U2(3));
        cross_gate<8>(pX, pY, 0b00001, pl,                     U2(4));
        reg_gate<0b1100, 0b0000>(pX, pY, pl,                   U2(5));
        reg_gate<0b0110, 0b1000>(pX, pY, pl,                   U2(6));
        reg_gate<0b0011, 0b1100>(pX, pY, pl,                   U2(7));
        hcross_gate<1, 0b1110>(pX, pY, pl,                     U2(8));
        pair_gate<0b1111>(pX, pY, pl,                          U2(9));
#undef U2
    }

    // ======= layer 2: twice-permuted coords (mask e_k ^ e_{k-2}) =============
    {
        const float4* Ub = &Us[2 * NQ];
#define U2(W) make_float2(Ub[(W)].x, Ub[(W)].y), make_float2(Ub[(W)].z, Ub[(W)].w)
        lane_gate(pX, pY, 0b10100, (lane >> 4) & 1,            U2(0));
        lane_gate(pX, pY, 0b01010, (lane >> 3) & 1,            U2(1));
        lane_gate(pX, pY, 0b00101, __popc(lane & 0b10100) & 1, U2(2));
        cross_gate<8>(pX, pY, 0b00010, pl2,                    U2(3));
        cross_gate<4>(pX, pY, 0b00001, pl3,                    U2(4));
        reg_gate<0b1010, 0b0000>(pX, pY, pl2,                  U2(5));
        reg_gate<0b0101, 0b0000>(pX, pY, pl3,                  U2(6));
        hcross_gate<2, 0b1000>(pX, pY, pl2,                    U2(7));
        reg_gate<0b0001, 0b0100>(pX, pY, pl3,                  U2(8));
        pair_gate<0b1010>(pX, pY, pl2,                         U2(9));
#undef U2
    }

    // ======= features: fold M^3 (three perms) into signs =====================
    const u64 Z64 = bc2(0.0f);
    u64 pt = Z64, c4 = Z64, c3 = Z64, c2 = Z64, c1 = Z64, c0 = Z64;
    const u64 bN1 = bc2(-1.0f);
#pragma unroll
    for (int m = 0; m < 16; m++) {
        u64 pp = fma2(pX[m], pX[m], mul2(pY[m], pY[m]));
        pt = add2(pt, pp);
        c4 = ((m >> 3) & 1)           ? fma2(pp, bN1, c4) : add2(c4, pp);
        c3 = (__popc(m & 0b1100) & 1) ? fma2(pp, bN1, c3) : add2(c3, pp);
        c2 = (__popc(m & 0b0110) & 1) ? fma2(pp, bN1, c2) : add2(c2, pp);
        c1 = (__popc(m & 0b0011) & 1) ? fma2(pp, bN1, c1) : add2(c1, pp);
        c0 = (__popc(m & 0b1001) & 1) ? fma2(pp, bN1, c0) : add2(c0, pp);
    }
    float lo, hi, ptot, A5, A6, A7, A8, A9;
    up2(pt, lo, hi);  ptot = lo + hi;
    up2(c4, lo, hi);  A5 = lo + hi;
    up2(c3, lo, hi);  A6 = lo + hi;
    up2(c2, lo, hi);  A7 = lo + hi;
    up2(c1, lo, hi);  A8 = lo + hi;
    up2(c0, lo, hi);  A9 = lo - hi;

    float g[NQ];
    g[0] = (__popc(lane & 0b10000) & 1) ? -ptot : ptot;
    g[1] = (__popc(lane & 0b11000) & 1) ? -ptot : ptot;
    g[2] = (__popc(lane & 0b01100) & 1) ? -ptot : ptot;
    g[3] = (__popc(lane & 0b00110) & 1) ? -ptot : ptot;
    g[4] = (__popc(lane & 0b10011) & 1) ? -ptot : ptot;
    g[5] = (__popc(lane & 0b11001) & 1) ? -A5 : A5;
    g[6] = (__popc(lane & 0b01100) & 1) ? -A6 : A6;
    g[7] = (__popc(lane & 0b00110) & 1) ? -A7 : A7;
    g[8] = (__popc(lane & 0b10011) & 1) ? -A8 : A8;
    g[9] = (__popc(lane & 0b11001) & 1) ? -A9 : A9;

#pragma unroll
    for (int i = 0; i < NQ; i++) {
#pragma unroll
        for (int o = 16; o > 0; o >>= 1)
            g[i] += __shfl_xor_sync(FULLM, g[i], o);
    }

    // ======= MLP 10 -> 32 -> 16 -> 1 =========================================
    float a1 = b1[lane];
#pragma unroll
    for (int i = 0; i < NQ; i++) a1 += g[i] * W1[i * 32 + lane];
    float h1v = tanhf(a1);

    float a2 = b2[lane & 15];
#pragma unroll
    for (int i = 0; i < 32; i++) {
        float h = __shfl_sync(FULLM, h1v, i);
        a2 += h * W2[i * 16 + (lane & 15)];
    }
    float h2v = tanhf(a2);

    float a3 = b3[0];
#pragma unroll
    for (int i = 0; i < 16; i++)
        a3 += __shfl_sync(FULLM, h2v, i) * W3[i];

    if (lane == 0) {
        float sg = 1.0f / (1.0f + expf(-a3));
        out[b] = sg * 0.2f - 0.1f;
    }
}

extern "C" void kernel_launch(void* const* d_in, const int* in_sizes, int n_in,
                              void* d_out, int out_size) {
    const float* z       = (const float*)d_in[0];
    const float* weights = (const float*)d_in[1];
    const float* W1      = (const float*)d_in[2];
    const float* b1      = (const float*)d_in[3];
    const float* W2      = (const float*)d_in[4];
    const float* b2      = (const float*)d_in[5];
    const float* W3      = (const float*)d_in[6];
    const float* b3      = (const float*)d_in[7];
    float* out           = (float*)d_out;

    const int B = in_sizes[0] / NQ;
    const int grid = (B + WPB - 1) / WPB;
    qgan_kernel<<<grid, THREADS>>>(z, weights, W1, b1, W2, b2, W3, b3, out, B);
}